// round 13
// baseline (speedup 1.0000x reference)
#include <cuda_runtime.h>
#include <cuda_bf16.h>
#include <math.h>
#include <stdint.h>

#define B_    1024
#define T_    512
#define BT_   (B_*T_)
#define IND   64
#define HD    128
#define G3    384
#define OD    64
#define NEG   0.01f
#define LNEPS 1e-5f

#define ASTR  136
#define SSTR  132

// ---------------- scratch ----------------
static __device__ float g_gates[(size_t)BT_ * G3];   // [B*T, 384]
static __device__ float g_y[(size_t)BT_ * HD];       // [B*T, 128]
static __device__ int   g_wordmode;

// pre-split bf16 weight planes
static __device__ __align__(16) __nv_bfloat16 g_w1h[HD * IND],  g_w1l[HD * IND];
static __device__ __align__(16) __nv_bfloat16 g_w2h[HD * HD],   g_w2l[HD * HD];
static __device__ __align__(16) __nv_bfloat16 g_wih_h[G3 * HD], g_wih_l[G3 * HD];
static __device__ __align__(16) __nv_bfloat16 g_wo_h[OD * HD],  g_wo_l[OD * HD];

__global__ void detect_kernel(const unsigned int* __restrict__ p) {
    __shared__ int bad;
    if (threadIdx.x == 0) bad = 0;
    __syncthreads();
    unsigned v = p[threadIdx.x];
    if (v != 0u && v != 1u && v != 0x3F800000u) atomicExch(&bad, 1);
    __syncthreads();
    if (threadIdx.x == 0) g_wordmode = bad ? 0 : 1;
}

__device__ __forceinline__ void splitw1(float v, __nv_bfloat16* h, __nv_bfloat16* l, int i) {
    __nv_bfloat16 hh = __float2bfloat16(v);
    h[i] = hh;
    l[i] = __float2bfloat16(v - __bfloat162float(hh));
}

// one-shot weight pre-split: 81920 elements
__global__ void prep_kernel(const float* __restrict__ W1, const float* __restrict__ W2,
                            const float* __restrict__ Wih, const float* __restrict__ Wout)
{
    int idx = blockIdx.x * blockDim.x + threadIdx.x;
    if (idx < 8192)                splitw1(W1[idx], g_w1h, g_w1l, idx);
    else if (idx < 24576)          { int i = idx - 8192;  splitw1(W2[i],  g_w2h,  g_w2l,  i); }
    else if (idx < 73728)          { int i = idx - 24576; splitw1(Wih[i], g_wih_h, g_wih_l, i); }
    else if (idx < 81920)          { int i = idx - 73728; splitw1(Wout[i], g_wo_h, g_wo_l, i); }
}

// ---------------- mma.sync helpers ----------------
__device__ __forceinline__ uint32_t smem_u32(const void* p) {
    uint32_t a;
    asm("{ .reg .u64 t; cvta.to.shared.u64 t, %1; cvt.u32.u64 %0, t; }" : "=r"(a) : "l"(p));
    return a;
}
__device__ __forceinline__ void ldsm_x4(uint32_t* r, uint32_t addr) {
    asm volatile("ldmatrix.sync.aligned.m8n8.x4.shared.b16 {%0,%1,%2,%3}, [%4];"
                 : "=r"(r[0]), "=r"(r[1]), "=r"(r[2]), "=r"(r[3]) : "r"(addr));
}
__device__ __forceinline__ void mma16816(float* d, const uint32_t* a, const uint32_t* b) {
    asm volatile("mma.sync.aligned.m16n8k16.row.col.f32.bf16.bf16.f32 "
                 "{%0,%1,%2,%3}, {%4,%5,%6,%7}, {%8,%9}, {%0,%1,%2,%3};"
                 : "+f"(d[0]), "+f"(d[1]), "+f"(d[2]), "+f"(d[3])
                 : "r"(a[0]), "r"(a[1]), "r"(a[2]), "r"(a[3]), "r"(b[0]), "r"(b[1]));
}

__device__ __forceinline__ void split2(__nv_bfloat16* hi, __nv_bfloat16* lo, int eo,
                                       float a, float b) {
    __nv_bfloat16 h0 = __float2bfloat16(a), h1 = __float2bfloat16(b);
    __nv_bfloat16 l0 = __float2bfloat16(a - __bfloat162float(h0));
    __nv_bfloat16 l1 = __float2bfloat16(b - __bfloat162float(h1));
    __nv_bfloat162 hh; hh.x = h0; hh.y = h1;
    __nv_bfloat162 ll; ll.x = l0; ll.y = l1;
    *(__nv_bfloat162*)(hi + eo) = hh;
    *(__nv_bfloat162*)(lo + eo) = ll;
}

// copy pre-split bf16 weights global -> smem (ASTR-padded rows), 16B chunks
template<int K, int NT>
__device__ __forceinline__ void load_wsplit(const __nv_bfloat16* __restrict__ gh,
                                            const __nv_bfloat16* __restrict__ gl,
                                            __nv_bfloat16* bh, __nv_bfloat16* bl,
                                            int rows, int tid)
{
    const int chunks = rows * (K / 8);
    for (int p = tid; p < chunks; p += NT) {
        int row = p / (K / 8), c = p % (K / 8);
        *(uint4*)(bh + row * ASTR + c * 8) = *(const uint4*)(gh + row * K + c * 8);
        *(uint4*)(bl + row * ASTR + c * 8) = *(const uint4*)(gl + row * K + c * 8);
    }
}

// ============================== FF: 512 threads, 16 warps ==============================
template<int NK>
__device__ __forceinline__ void wgemm512(uint32_t a_hi, uint32_t a_lo,
                                         uint32_t b_hi, uint32_t b_lo,
                                         float (*acc)[4], int warp, int lane)
{
    const int wr = warp & 7, ch = warp >> 3;
    const int arow = 16 * wr + (lane & 7) + ((lane & 8) ? 8 : 0);
    const int acg  = (lane & 16) ? 8 : 0;
    const uint32_t aoff = (uint32_t)(arow * ASTR + acg) * 2;
    const int nloc = ch * 64 + (lane & 7) + ((lane & 16) ? 8 : 0);
    const int bkg  = (lane & 8) ? 8 : 0;
    const uint32_t boff = (uint32_t)(nloc * ASTR + bkg) * 2;
    #pragma unroll
    for (int k0 = 0; k0 < NK; k0++) {
        uint32_t ah[4], al[4];
        ldsm_x4(ah, a_hi + aoff + k0 * 32);
        ldsm_x4(al, a_lo + aoff + k0 * 32);
        #pragma unroll
        for (int jp = 0; jp < 4; jp++) {
            uint32_t bo = boff + (uint32_t)(jp * 16 * ASTR) * 2 + k0 * 32;
            uint32_t bh[4], bl[4];
            ldsm_x4(bh, b_hi + bo);
            ldsm_x4(bl, b_lo + bo);
            mma16816(acc[2*jp],     ah, bh);
            mma16816(acc[2*jp],     ah, bl);
            mma16816(acc[2*jp],     al, bh);
            mma16816(acc[2*jp + 1], ah, bh + 2);
            mma16816(acc[2*jp + 1], ah, bl + 2);
            mma16816(acc[2*jp + 1], al, bh + 2);
        }
    }
}

__device__ __forceinline__ void ln_epi512(float (*acc)[4],
    const float* __restrict__ bias, const float* __restrict__ gam, const float* __restrict__ bet,
    __nv_bfloat16* Ah, __nv_bfloat16* Al, int warp, int lane,
    float* psum, float* psq)
{
    const int wr = warp & 7, ch = warp >> 3, cb = ch * 64;
    const int r0 = 16 * wr + (lane >> 2), r1 = r0 + 8;
    float s0 = 0.f, q0 = 0.f, s1 = 0.f, q1 = 0.f;
    #pragma unroll
    for (int j = 0; j < 8; j++) {
        int col = cb + 8 * j + 2 * (lane & 3);
        float bv0 = __ldg(&bias[col]), bv1 = __ldg(&bias[col + 1]);
        float v00 = acc[j][0] + bv0; v00 = v00 > 0.f ? v00 : NEG * v00;
        float v01 = acc[j][1] + bv1; v01 = v01 > 0.f ? v01 : NEG * v01;
        float v10 = acc[j][2] + bv0; v10 = v10 > 0.f ? v10 : NEG * v10;
        float v11 = acc[j][3] + bv1; v11 = v11 > 0.f ? v11 : NEG * v11;
        acc[j][0] = v00; acc[j][1] = v01; acc[j][2] = v10; acc[j][3] = v11;
        s0 += v00 + v01; q0 += v00 * v00 + v01 * v01;
        s1 += v10 + v11; q1 += v10 * v10 + v11 * v11;
    }
    s0 += __shfl_xor_sync(0xffffffffu, s0, 1); s0 += __shfl_xor_sync(0xffffffffu, s0, 2);
    q0 += __shfl_xor_sync(0xffffffffu, q0, 1); q0 += __shfl_xor_sync(0xffffffffu, q0, 2);
    s1 += __shfl_xor_sync(0xffffffffu, s1, 1); s1 += __shfl_xor_sync(0xffffffffu, s1, 2);
    q1 += __shfl_xor_sync(0xffffffffu, q1, 1); q1 += __shfl_xor_sync(0xffffffffu, q1, 2);
    psum[ch * 128 + r0] = s0; psq[ch * 128 + r0] = q0;
    psum[ch * 128 + r1] = s1; psq[ch * 128 + r1] = q1;
    __syncthreads();
    float st0 = psum[r0] + psum[128 + r0], qt0 = psq[r0] + psq[128 + r0];
    float st1 = psum[r1] + psum[128 + r1], qt1 = psq[r1] + psq[128 + r1];
    float mu0 = st0 * (1.f / 128.f), rs0 = rsqrtf(qt0 * (1.f / 128.f) - mu0 * mu0 + LNEPS);
    float mu1 = st1 * (1.f / 128.f), rs1 = rsqrtf(qt1 * (1.f / 128.f) - mu1 * mu1 + LNEPS);
    #pragma unroll
    for (int j = 0; j < 8; j++) {
        int col = cb + 8 * j + 2 * (lane & 3);
        float g0 = __ldg(&gam[col]), g1 = __ldg(&gam[col + 1]);
        float t0 = __ldg(&bet[col]), t1 = __ldg(&bet[col + 1]);
        split2(Ah, Al, r0 * ASTR + col,
               (acc[j][0] - mu0) * rs0 * g0 + t0, (acc[j][1] - mu0) * rs0 * g1 + t1);
        split2(Ah, Al, r1 * ASTR + col,
               (acc[j][2] - mu1) * rs1 * g0 + t0, (acc[j][3] - mu1) * rs1 * g1 + t1);
    }
}

// direct fragment -> global gates store (no stage)
__device__ __forceinline__ void gates_epi_direct(float (*acc)[4], const float* __restrict__ bias,
                                                 float* __restrict__ gout, int warp, int lane)
{
    const int wr = warp & 7, ch = warp >> 3, cb = ch * 64;
    const int r0 = 16 * wr + (lane >> 2), r1 = r0 + 8;
    #pragma unroll
    for (int j = 0; j < 8; j++) {
        int col = cb + 8 * j + 2 * (lane & 3);
        float bv0 = __ldg(&bias[col]), bv1 = __ldg(&bias[col + 1]);
        *(float2*)&gout[(size_t)r0 * G3 + col] = make_float2(acc[j][0] + bv0, acc[j][1] + bv1);
        *(float2*)&gout[(size_t)r1 * G3 + col] = make_float2(acc[j][2] + bv0, acc[j][3] + bv1);
    }
}

#define SM_AH   0
#define SM_AL   (128 * ASTR * 2)
#define SM_BH   (2 * 128 * ASTR * 2)
#define SM_BL   (3 * 128 * ASTR * 2)
#define SM_PS   (4 * 128 * ASTR * 2)
#define SM_TOT  (SM_PS + 4 * 256 * 4)

__global__ void __launch_bounds__(512) ff_kernel(
    const float* __restrict__ x,
    const float* __restrict__ b1, const float* __restrict__ g1, const float* __restrict__ be1,
    const float* __restrict__ b2, const float* __restrict__ g2, const float* __restrict__ be2,
    const float* __restrict__ bih)
{
    extern __shared__ char smem[];
    __nv_bfloat16* Ah = (__nv_bfloat16*)(smem + SM_AH);
    __nv_bfloat16* Al = (__nv_bfloat16*)(smem + SM_AL);
    __nv_bfloat16* Bh = (__nv_bfloat16*)(smem + SM_BH);
    __nv_bfloat16* Bl = (__nv_bfloat16*)(smem + SM_BL);
    float* psum = (float*)(smem + SM_PS);
    float* psq  = psum + 256;
    const uint32_t a_hi = smem_u32(Ah), a_lo = smem_u32(Al);
    const uint32_t b_hi = smem_u32(Bh), b_lo = smem_u32(Bl);
    const int tid = threadIdx.x, warp = tid >> 5, lane = tid & 31;
    const size_t base = (size_t)blockIdx.x * 128;

    for (int p = tid; p < 128 * 32; p += 512) {
        int row = p >> 5, kp = p & 31;
        float2 v = *(const float2*)&x[(base + row) * IND + 2 * kp];
        split2(Ah, Al, row * ASTR + 2 * kp, v.x, v.y);
    }
    load_wsplit<IND, 512>(g_w1h, g_w1l, Bh, Bl, 128, tid);
    __syncthreads();

    float acc[8][4];
    #pragma unroll
    for (int j = 0; j < 8; j++) { acc[j][0]=acc[j][1]=acc[j][2]=acc[j][3]=0.f; }
    wgemm512<4>(a_hi, a_lo, b_hi, b_lo, acc, warp, lane);
    __syncthreads();
    ln_epi512(acc, b1, g1, be1, Ah, Al, warp, lane, psum, psq);

    load_wsplit<HD, 512>(g_w2h, g_w2l, Bh, Bl, 128, tid);
    __syncthreads();
    #pragma unroll
    for (int j = 0; j < 8; j++) { acc[j][0]=acc[j][1]=acc[j][2]=acc[j][3]=0.f; }
    wgemm512<8>(a_hi, a_lo, b_hi, b_lo, acc, warp, lane);
    __syncthreads();
    ln_epi512(acc, b2, g2, be2, Ah, Al, warp, lane, psum, psq);

    for (int c3 = 0; c3 < 3; c3++) {
        load_wsplit<HD, 512>(g_wih_h + (size_t)c3 * 128 * HD, g_wih_l + (size_t)c3 * 128 * HD,
                             Bh, Bl, 128, tid);
        __syncthreads();
        #pragma unroll
        for (int j = 0; j < 8; j++) { acc[j][0]=acc[j][1]=acc[j][2]=acc[j][3]=0.f; }
        wgemm512<8>(a_hi, a_lo, b_hi, b_lo, acc, warp, lane);
        gates_epi_direct(acc, bih + c3 * 128, g_gates + base * G3 + c3 * 128, warp, lane);
        __syncthreads();   // before next chunk overwrites Bh/Bl
    }
}

// ============================== REC v6: cluster-2 j-split + k-split + cp.async gx ==============================
#define RSM_WH  0
#define RSM_WL  49152
#define RSM_A   98304                      // 2 bufs x (hi 4096 + lo 4096)
#define RSM_P   (RSM_A + 16384)            // partials 12288
#define RSM_GX  (RSM_P + 12288)            // 2 bufs x 16 x 388 floats = 49664
#define RSM_MB  (RSM_GX + 49664)
#define RSM_TOT (RSM_MB + 16)              // 176656

#define GXBUF_B 24832                      // bytes per buffer
#define GXBUF_F 6208                       // floats per buffer
#define GXROW_F 388                        // floats per batch row

__device__ __forceinline__ float sigf(float x) {
    float e = __expf(-x);
    return __fdividef(1.f, 1.f + e);
}
__device__ __forceinline__ float tanhf_fast(float x) {
    return fmaf(2.f, sigf(2.f * x), -1.f);
}

#define MBAR_INIT(m, n)  asm volatile("mbarrier.init.shared.b64 [%0], %1;" :: "r"(m), "r"(n) : "memory")
#define MBAR_ARRIVE_LOCAL(m) \
    asm volatile("mbarrier.arrive.release.cluster.shared::cta.b64 _, [%0];" :: "r"(m) : "memory")
#define MBAR_ARRIVE_REMOTE(m) \
    asm volatile("mbarrier.arrive.release.cluster.shared::cluster.b64 _, [%0];" :: "r"(m) : "memory")
#define MBAR_WAIT_CL(mb, ph) do {                                              \
    uint32_t _m = (mb); uint32_t _p = (ph); uint32_t _d;                       \
    asm volatile("{\n\t.reg .pred p;\n\t"                                      \
        "mbarrier.try_wait.parity.acquire.cluster.shared::cta.b64 p, [%1], %2;\n\t" \
        "selp.b32 %0, 1, 0, p;\n\t}"                                           \
        : "=r"(_d) : "r"(_m), "r"(_p) : "memory");                             \
    if (!_d) {                                                                 \
        asm volatile("{\n\t.reg .pred P1;\n\t"                                 \
            "W_%=:\n\t"                                                        \
            "mbarrier.try_wait.parity.acquire.cluster.shared::cta.b64 P1, [%0], %1, 0x989680;\n\t" \
            "@P1 bra.uni D_%=;\n\tbra.uni W_%=;\n\tD_%=:\n\t}"                 \
            :: "r"(_m), "r"(_p) : "memory");                                   \
    }                                                                          \
} while (0)

__device__ __forceinline__ void stA2_both(char* AHl, uint32_t AHp, int b, int j, float2 h) {
    uint32_t off = (uint32_t)(b * 256 + (((j >> 3) ^ (b & 7)) << 4) + (j & 7) * 2);
    __nv_bfloat16 h0 = __float2bfloat16(h.x), h1 = __float2bfloat16(h.y);
    __nv_bfloat16 l0 = __float2bfloat16(h.x - __bfloat162float(h0));
    __nv_bfloat16 l1 = __float2bfloat16(h.y - __bfloat162float(h1));
    __nv_bfloat162 hh; hh.x = h0; hh.y = h1;
    __nv_bfloat162 ll; ll.x = l0; ll.y = l1;
    uint32_t hw = *(uint32_t*)&hh, lw = *(uint32_t*)&ll;
    *(uint32_t*)(AHl + off) = hw;
    *(uint32_t*)(AHl + 4096 + off) = lw;
    asm volatile("st.shared::cluster.u32 [%0], %1;" :: "r"(AHp + off), "r"(hw) : "memory");
    asm volatile("st.shared::cluster.u32 [%0], %1;" :: "r"(AHp + 4096 + off), "r"(lw) : "memory");
}

__global__ void __launch_bounds__(512, 1) __cluster_dims__(2, 1, 1)
rec_kernel(
    const float* __restrict__ hx, const float* __restrict__ Whh,
    const float* __restrict__ bhh, const void* __restrict__ isinit,
    float* __restrict__ hxout)
{
    extern __shared__ char sm[];
    char* WH = sm + RSM_WH;
    char* WL = sm + RSM_WL;
    const uint32_t whb = smem_u32(WH), wlb = smem_u32(WL);
    const uint32_t aab = smem_u32(sm + RSM_A);
    const uint32_t mbar = smem_u32(sm + RSM_MB);
    float* Pbuf = (float*)(sm + RSM_P);
    float* GX   = (float*)(sm + RSM_GX);
    const uint32_t gxu = smem_u32(GX);
    const int tid = threadIdx.x, warp = tid >> 5, lane = tid & 31;
    const int wr = warp & 7, kh = warp >> 3;

    uint32_t rank;
    asm("mov.u32 %0, %%cluster_ctarank;" : "=r"(rank));
    const uint32_t peer = rank ^ 1u;
    const int b0 = (blockIdx.x >> 1) * 16;
    const int jhalf = (int)rank * 64;

    uint32_t aab_peer, mbar_peer;
    asm("mapa.shared::cluster.u32 %0, %1, %2;" : "=r"(aab_peer)  : "r"(aab),  "r"(peer));
    asm("mapa.shared::cluster.u32 %0, %1, %2;" : "=r"(mbar_peer) : "r"(mbar), "r"(peer));

    if (tid == 0) MBAR_INIT(mbar, 2);

    // W_hh conversion: this rank's 192 gate-column rows
    for (int p = tid; p < 192 * 64; p += 512) {
        int row_local = p >> 6, kp = p & 63, k = 2 * kp;
        int g = row_local >> 6, jn = row_local & 63;
        int grow = (g << 7) + jhalf + jn;
        float2 v = *(const float2*)&Whh[grow * 128 + k];
        uint32_t off = (uint32_t)(row_local * 256 + (((k >> 3) ^ (row_local & 7)) << 4) + (k & 7) * 2);
        split2((__nv_bfloat16*)(WH + off), (__nv_bfloat16*)(WL + off), 0, v.x, v.y);
    }

    // thread coords: batch b = (lane>>2) + 8*kh; cols j_g, j_g+1
    const int b = (lane >> 2) + 8 * kh;
    const int j_g = jhalf + 8 * wr + 2 * (lane & 3);

    float bv[3][2];
    #pragma unroll
    for (int g = 0; g < 3; g++) {
        int col = g * 128 + j_g;
        bv[g][0] = __ldg(&bhh[col]);
        bv[g][1] = __ldg(&bhh[col + 1]);
    }

    const int wm = g_wordmode;
    const unsigned int*  ii32 = (const unsigned int*)isinit;
    const unsigned char* ii8  = (const unsigned char*)isinit;

    // cp.async gx staging: thread handles 3 float4 chunks
    const float* gsrc[3];
    uint32_t gdst[3];
    #pragma unroll
    for (int s = 0; s < 3; s++) {
        int flat = tid + s * 512;            // 0..1535
        int bq = flat / 96, cq = flat - 96 * bq;
        gsrc[s] = g_gates + (size_t)(b0 + bq) * T_ * G3 + cq * 4;
        gdst[s] = (uint32_t)(bq * (GXROW_F * 4) + cq * 16);
    }

    // A0 build + issue gx(t=0) into buffer 0
    float hprev[2];
    {
        char* AH0 = sm + RSM_A;
        size_t ib = (size_t)(b0 + b) * T_;
        int f0 = wm ? (ii32[ib] != 0u) : (ii8[ib] != 0);
        float2 v = *(const float2*)&hx[(size_t)(b0 + b) * HD + j_g];
        if (f0) { v.x = 0.f; v.y = 0.f; }
        hprev[0] = v.x; hprev[1] = v.y;
        stA2_both(AH0, aab_peer, b, j_g, v);
        #pragma unroll
        for (int s = 0; s < 3; s++)
            asm volatile("cp.async.ca.shared.global [%0], [%1], 16;"
                         :: "r"(gxu + gdst[s]), "l"(gsrc[s]) : "memory");
        asm volatile("cp.async.commit_group;" ::: "memory");
    }

    asm volatile("barrier.cluster.arrive.aligned;" ::: "memory");
    asm volatile("barrier.cluster.wait.aligned;" ::: "memory");

    // ldmatrix addressing
    const int arow = lane & 15;
    const uint32_t abase = (uint32_t)(arow * 256);
    const int achx = (lane & 16) ? 1 : 0, arx = arow & 7;
    const int nrl = 8 * wr + (lane & 7);
    const int kc = lane >> 3;

    // partial-exchange slots
    const int pub_slot  = ((kh * 8 + wr) * 32 + lane) * 6;
    const int read_slot = (((1 - kh) * 8 + wr) * 32 + lane) * 6;

    int cur = 0;
    for (int t = 0; t < T_; t++) {
        const int nxt = cur ^ 1;
        // issue gx(t+1) into next buffer + prefetch flag
        int nf = 0;
        if (t + 1 < T_) {
            const size_t toff = (size_t)(t + 1) * G3;
            #pragma unroll
            for (int s = 0; s < 3; s++)
                asm volatile("cp.async.ca.shared.global [%0], [%1], 16;"
                             :: "r"(gxu + (uint32_t)nxt * GXBUF_B + gdst[s]),
                                "l"(gsrc[s] + toff) : "memory");
            asm volatile("cp.async.commit_group;" ::: "memory");
            size_t ib = (size_t)(b0 + b) * T_ + (t + 1);
            nf = wm ? (ii32[ib] != 0u) : (ii8[ib] != 0);
        }

        // ---- MMA over this warp's k-half: 2 k32 blocks ----
        float acc[3][4];
        #pragma unroll
        for (int g = 0; g < 3; g++) { acc[g][0]=acc[g][1]=acc[g][2]=acc[g][3]=0.f; }
        const uint32_t ahb = aab + (uint32_t)cur * 8192;
        const uint32_t alb = ahb + 4096;
        #pragma unroll
        for (int kkl = 0; kkl < 2; kkl++) {
            const int kk = 2 * kh + kkl;
            uint32_t ah4[2][4], al4[2][4];
            #pragma unroll
            for (int s = 0; s < 2; s++) {
                int k0 = 2 * kk + s;
                uint32_t ach = (uint32_t)((2 * k0 + achx) ^ arx);
                ldsm_x4(ah4[s], ahb + abase + (ach << 4));
                ldsm_x4(al4[s], alb + abase + (ach << 4));
            }
            #pragma unroll
            for (int g = 0; g < 3; g++) {
                int row_local = (g << 6) + nrl;
                uint32_t chunk = (uint32_t)((4 * kk + kc) ^ (lane & 7));
                uint32_t boff = (uint32_t)(row_local * 256) + (chunk << 4);
                uint32_t bh4[4], bl4[4];
                ldsm_x4(bh4, whb + boff);
                ldsm_x4(bl4, wlb + boff);
                #pragma unroll
                for (int s = 0; s < 2; s++) {
                    mma16816(acc[g], ah4[s], bh4 + 2 * s);
                    mma16816(acc[g], ah4[s], bl4 + 2 * s);
                    mma16816(acc[g], al4[s], bh4 + 2 * s);
                }
            }
        }

        // publish partials for peer k-half
        {
            const int pix = 2 * (1 - kh);
            #pragma unroll
            for (int g = 0; g < 3; g++) {
                Pbuf[pub_slot + 2 * g]     = acc[g][pix];
                Pbuf[pub_slot + 2 * g + 1] = acc[g][pix + 1];
            }
        }
        // gx(t) must be resident before epilogue reads it
        if (t + 1 < T_) asm volatile("cp.async.wait_group 1;" ::: "memory");
        else            asm volatile("cp.async.wait_group 0;" ::: "memory");
        __syncthreads();

        // ---- epilogue ----
        char* AHn = sm + RSM_A + nxt * 8192;
        uint32_t pAHn = aab_peer + (uint32_t)nxt * 8192;
        const float* gxrow = GX + (size_t)cur * GXBUF_F + b * GXROW_F;
        float2 gx0 = *(const float2*)&gxrow[j_g];
        float2 gx1 = *(const float2*)&gxrow[128 + j_g];
        float2 gx2 = *(const float2*)&gxrow[256 + j_g];
        float hn_[2];
        #pragma unroll
        for (int q = 0; q < 2; q++) {
            const int ix = 2 * kh + q;
            float a0 = acc[0][ix] + Pbuf[read_slot + 0 + q] + bv[0][q];
            float a1 = acc[1][ix] + Pbuf[read_slot + 2 + q] + bv[1][q];
            float a2 = acc[2][ix] + Pbuf[read_slot + 4 + q] + bv[2][q];
            float gxr = q ? gx0.y : gx0.x;
            float gxz = q ? gx1.y : gx1.x;
            float gxn = q ? gx2.y : gx2.x;
            float rr = sigf(gxr + a0);
            float zz = sigf(gxz + a1);
            float nn = tanhf_fast(gxn + rr * a2);
            hn_[q] = (1.f - zz) * nn + zz * hprev[q];
        }
        *(float2*)&g_y[((size_t)(b0 + b) * T_ + t) * HD + j_g] = make_float2(hn_[0], hn_[1]);
        if (t + 1 < T_) {
            float2 he = nf ? make_float2(0.f, 0.f) : make_float2(hn_[0], hn_[1]);
            hprev[0] = he.x; hprev[1] = he.y;
            stA2_both(AHn, pAHn, b, j_g, he);

            __syncthreads();
            if (tid == 0) {
                MBAR_ARRIVE_LOCAL(mbar);
                MBAR_ARRIVE_REMOTE(mbar_peer);
            }
            MBAR_WAIT_CL(mbar, (uint32_t)(t & 1));
        } else {
            *(float2*)&hxout[(size_t)(b0 + b) * HD + j_g] = make_float2(hn_[0], hn_[1]);
        }
        cur = nxt;
    }
}

// ---------------- out: 256 threads (R9 structure, pre-split Wout) ----------------
#define OSM_AH  0
#define OSM_AL  (128 * ASTR * 2)
#define OSM_BH  (2 * 128 * ASTR * 2)
#define OSM_BL  (OSM_BH + 64 * ASTR * 2)
#define OSM_TOT (OSM_BH + 2 * 64 * ASTR * 2)

__global__ void __launch_bounds__(256, 2) out_kernel(
    const float* __restrict__ bout, float* __restrict__ out)
{
    extern __shared__ char smem[];
    __nv_bfloat16* Ah = (__nv_bfloat16*)(smem + OSM_AH);
    __nv_bfloat16* Al = (__nv_bfloat16*)(smem + OSM_AL);
    __nv_bfloat16* Bh = (__nv_bfloat16*)(smem + OSM_BH);
    __nv_bfloat16* Bl = (__nv_bfloat16*)(smem + OSM_BL);
    const uint32_t a_hi = smem_u32(Ah), a_lo = smem_u32(Al);
    const uint32_t b_hi = smem_u32(Bh), b_lo = smem_u32(Bl);
    const int tid = threadIdx.x, warp = tid >> 5, lane = tid & 31;
    const size_t base = (size_t)blockIdx.x * 128;

    for (int p = tid; p < 128 * 64; p += 256) {
        int row = p >> 6, kp = p & 63;
        float2 v = *(const float2*)&g_y[(base + row) * HD + 2 * kp];
        split2(Ah, Al, row * ASTR + 2 * kp, v.x, v.y);
    }
    load_wsplit<HD, 256>(g_wo_h, g_wo_l, Bh, Bl, 64, tid);
    __syncthreads();

    float acc[8][4];
    #pragma unroll
    for (int j = 0; j < 8; j++) { acc[j][0]=acc[j][1]=acc[j][2]=acc[j][3]=0.f; }

    const int arow = 16 * warp + (lane & 7) + ((lane & 8) ? 8 : 0);
    const int acg  = (lane & 16) ? 8 : 0;
    const uint32_t aoff = (uint32_t)(arow * ASTR + acg) * 2;
    const int nloc = (lane & 7) + ((lane & 16) ? 8 : 0);
    const int bkg  = (lane & 8) ? 8 : 0;
    const uint32_t boff = (uint32_t)(nloc * ASTR + bkg) * 2;
    #pragma unroll
    for (int k0 = 0; k0 < 8; k0++) {
        uint32_t ah[4], al[4];
        ldsm_x4(ah, a_hi + aoff + k0 * 32);
        ldsm_x4(al, a_lo + aoff + k0 * 32);
        #pragma unroll
        for (int jp = 0; jp < 4; jp++) {
            uint32_t bo = boff + (uint32_t)(jp * 16 * ASTR) * 2 + k0 * 32;
            uint32_t bh[4], bl[4];
            ldsm_x4(bh, b_hi + bo);
            ldsm_x4(bl, b_lo + bo);
            mma16816(acc[2*jp],     ah, bh);
            mma16816(acc[2*jp],     ah, bl);
            mma16816(acc[2*jp],     al, bh);
            mma16816(acc[2*jp + 1], ah, bh + 2);
            mma16816(acc[2*jp + 1], ah, bl + 2);
            mma16816(acc[2*jp + 1], al, bh + 2);
        }
    }

    const int r0 = 16 * warp + (lane >> 2), r1 = r0 + 8;
    #pragma unroll
    for (int j = 0; j < 8; j++) {
        int col = 8 * j + 2 * (lane & 3);
        float bv0 = __ldg(&bout[col]), bv1 = __ldg(&bout[col + 1]);
        *(float2*)&out[(base + r0) * OD + col] = make_float2(acc[j][0] + bv0, acc[j][1] + bv1);
        *(float2*)&out[(base + r1) * OD + col] = make_float2(acc[j][2] + bv0, acc[j][3] + bv1);
    }
}

// ---------------- launcher ----------------
extern "C" void kernel_launch(void* const* d_in, const int* in_sizes, int n_in,
                              void* d_out, int out_size)
{
    const float* x    = (const float*)d_in[0];
    const void*  isin = d_in[1];
    const float* hx   = (const float*)d_in[2];
    const float* W1   = (const float*)d_in[3];
    const float* b1   = (const float*)d_in[4];
    const float* g1   = (const float*)d_in[5];
    const float* be1  = (const float*)d_in[6];
    const float* W2   = (const float*)d_in[7];
    const float* b2   = (const float*)d_in[8];
    const float* g2   = (const float*)d_in[9];
    const float* be2  = (const float*)d_in[10];
    const float* Wih  = (const float*)d_in[11];
    const float* Whh  = (const float*)d_in[12];
    const float* bih  = (const float*)d_in[13];
    const float* bhh  = (const float*)d_in[14];
    const float* Wout = (const float*)d_in[15];
    const float* bout = (const float*)d_in[16];
    float* out = (float*)d_out;

    cudaFuncSetAttribute(ff_kernel,  cudaFuncAttributeMaxDynamicSharedMemorySize, SM_TOT);
    cudaFuncSetAttribute(rec_kernel, cudaFuncAttributeMaxDynamicSharedMemorySize, RSM_TOT);
    cudaFuncSetAttribute(out_kernel, cudaFuncAttributeMaxDynamicSharedMemorySize, OSM_TOT);

    detect_kernel<<<1, 256>>>((const unsigned int*)isin);
    prep_kernel<<<160, 512>>>(W1, W2, Wih, Wout);
    ff_kernel<<<BT_ / 128, 512, SM_TOT>>>(x, b1, g1, be1, b2, g2, be2, bih);
    rec_kernel<<<128, 512, RSM_TOT>>>(hx, Whh, bhh, isin, out + (size_t)BT_ * OD);
    out_kernel<<<BT_ / 128, 256, OSM_TOT>>>(bout, out);
}

// round 14
// speedup vs baseline: 1.0892x; 1.0892x over previous
#include <cuda_runtime.h>
#include <cuda_bf16.h>
#include <math.h>
#include <stdint.h>

#define B_    1024
#define T_    512
#define BT_   (B_*T_)
#define IND   64
#define HD    128
#define G3    384
#define OD    64
#define NEG   0.01f
#define LNEPS 1e-5f

#define ASTR  136
#define SSTR  132

// ---------------- scratch ----------------
static __device__ float g_gates[(size_t)BT_ * G3];   // [B*T, 384]
static __device__ float g_y[(size_t)BT_ * HD];       // [B*T, 128]
static __device__ int   g_wordmode;

// pre-split bf16 weight planes
static __device__ __align__(16) __nv_bfloat16 g_w1h[HD * IND],  g_w1l[HD * IND];
static __device__ __align__(16) __nv_bfloat16 g_w2h[HD * HD],   g_w2l[HD * HD];
static __device__ __align__(16) __nv_bfloat16 g_wih_h[G3 * HD], g_wih_l[G3 * HD];
static __device__ __align__(16) __nv_bfloat16 g_wo_h[OD * HD],  g_wo_l[OD * HD];

__global__ void detect_kernel(const unsigned int* __restrict__ p) {
    __shared__ int bad;
    if (threadIdx.x == 0) bad = 0;
    __syncthreads();
    unsigned v = p[threadIdx.x];
    if (v != 0u && v != 1u && v != 0x3F800000u) atomicExch(&bad, 1);
    __syncthreads();
    if (threadIdx.x == 0) g_wordmode = bad ? 0 : 1;
}

__device__ __forceinline__ void splitw1(float v, __nv_bfloat16* h, __nv_bfloat16* l, int i) {
    __nv_bfloat16 hh = __float2bfloat16(v);
    h[i] = hh;
    l[i] = __float2bfloat16(v - __bfloat162float(hh));
}

// one-shot weight pre-split: 81920 elements
__global__ void prep_kernel(const float* __restrict__ W1, const float* __restrict__ W2,
                            const float* __restrict__ Wih, const float* __restrict__ Wout)
{
    int idx = blockIdx.x * blockDim.x + threadIdx.x;
    if (idx < 8192)                splitw1(W1[idx], g_w1h, g_w1l, idx);
    else if (idx < 24576)          { int i = idx - 8192;  splitw1(W2[i],  g_w2h,  g_w2l,  i); }
    else if (idx < 73728)          { int i = idx - 24576; splitw1(Wih[i], g_wih_h, g_wih_l, i); }
    else if (idx < 81920)          { int i = idx - 73728; splitw1(Wout[i], g_wo_h, g_wo_l, i); }
}

// ---------------- mma.sync helpers ----------------
__device__ __forceinline__ uint32_t smem_u32(const void* p) {
    uint32_t a;
    asm("{ .reg .u64 t; cvta.to.shared.u64 t, %1; cvt.u32.u64 %0, t; }" : "=r"(a) : "l"(p));
    return a;
}
__device__ __forceinline__ void ldsm_x4(uint32_t* r, uint32_t addr) {
    asm volatile("ldmatrix.sync.aligned.m8n8.x4.shared.b16 {%0,%1,%2,%3}, [%4];"
                 : "=r"(r[0]), "=r"(r[1]), "=r"(r[2]), "=r"(r[3]) : "r"(addr));
}
__device__ __forceinline__ void mma16816(float* d, const uint32_t* a, const uint32_t* b) {
    asm volatile("mma.sync.aligned.m16n8k16.row.col.f32.bf16.bf16.f32 "
                 "{%0,%1,%2,%3}, {%4,%5,%6,%7}, {%8,%9}, {%0,%1,%2,%3};"
                 : "+f"(d[0]), "+f"(d[1]), "+f"(d[2]), "+f"(d[3])
                 : "r"(a[0]), "r"(a[1]), "r"(a[2]), "r"(a[3]), "r"(b[0]), "r"(b[1]));
}

__device__ __forceinline__ void split2(__nv_bfloat16* hi, __nv_bfloat16* lo, int eo,
                                       float a, float b) {
    __nv_bfloat16 h0 = __float2bfloat16(a), h1 = __float2bfloat16(b);
    __nv_bfloat16 l0 = __float2bfloat16(a - __bfloat162float(h0));
    __nv_bfloat16 l1 = __float2bfloat16(b - __bfloat162float(h1));
    __nv_bfloat162 hh; hh.x = h0; hh.y = h1;
    __nv_bfloat162 ll; ll.x = l0; ll.y = l1;
    *(__nv_bfloat162*)(hi + eo) = hh;
    *(__nv_bfloat162*)(lo + eo) = ll;
}

// copy pre-split bf16 weights global -> smem (ASTR-padded rows), 16B chunks
template<int K, int NT>
__device__ __forceinline__ void load_wsplit(const __nv_bfloat16* __restrict__ gh,
                                            const __nv_bfloat16* __restrict__ gl,
                                            __nv_bfloat16* bh, __nv_bfloat16* bl,
                                            int rows, int tid)
{
    const int chunks = rows * (K / 8);
    for (int p = tid; p < chunks; p += NT) {
        int row = p / (K / 8), c = p % (K / 8);
        *(uint4*)(bh + row * ASTR + c * 8) = *(const uint4*)(gh + row * K + c * 8);
        *(uint4*)(bl + row * ASTR + c * 8) = *(const uint4*)(gl + row * K + c * 8);
    }
}

// ============================== FF: 512 threads, 16 warps ==============================
template<int NK>
__device__ __forceinline__ void wgemm512(uint32_t a_hi, uint32_t a_lo,
                                         uint32_t b_hi, uint32_t b_lo,
                                         float (*acc)[4], int warp, int lane)
{
    const int wr = warp & 7, ch = warp >> 3;
    const int arow = 16 * wr + (lane & 7) + ((lane & 8) ? 8 : 0);
    const int acg  = (lane & 16) ? 8 : 0;
    const uint32_t aoff = (uint32_t)(arow * ASTR + acg) * 2;
    const int nloc = ch * 64 + (lane & 7) + ((lane & 16) ? 8 : 0);
    const int bkg  = (lane & 8) ? 8 : 0;
    const uint32_t boff = (uint32_t)(nloc * ASTR + bkg) * 2;
    #pragma unroll
    for (int k0 = 0; k0 < NK; k0++) {
        uint32_t ah[4], al[4];
        ldsm_x4(ah, a_hi + aoff + k0 * 32);
        ldsm_x4(al, a_lo + aoff + k0 * 32);
        #pragma unroll
        for (int jp = 0; jp < 4; jp++) {
            uint32_t bo = boff + (uint32_t)(jp * 16 * ASTR) * 2 + k0 * 32;
            uint32_t bh[4], bl[4];
            ldsm_x4(bh, b_hi + bo);
            ldsm_x4(bl, b_lo + bo);
            mma16816(acc[2*jp],     ah, bh);
            mma16816(acc[2*jp],     ah, bl);
            mma16816(acc[2*jp],     al, bh);
            mma16816(acc[2*jp + 1], ah, bh + 2);
            mma16816(acc[2*jp + 1], ah, bl + 2);
            mma16816(acc[2*jp + 1], al, bh + 2);
        }
    }
}

__device__ __forceinline__ void ln_epi512(float (*acc)[4],
    const float* __restrict__ bias, const float* __restrict__ gam, const float* __restrict__ bet,
    __nv_bfloat16* Ah, __nv_bfloat16* Al, int warp, int lane,
    float* psum, float* psq)
{
    const int wr = warp & 7, ch = warp >> 3, cb = ch * 64;
    const int r0 = 16 * wr + (lane >> 2), r1 = r0 + 8;
    float s0 = 0.f, q0 = 0.f, s1 = 0.f, q1 = 0.f;
    #pragma unroll
    for (int j = 0; j < 8; j++) {
        int col = cb + 8 * j + 2 * (lane & 3);
        float bv0 = __ldg(&bias[col]), bv1 = __ldg(&bias[col + 1]);
        float v00 = acc[j][0] + bv0; v00 = v00 > 0.f ? v00 : NEG * v00;
        float v01 = acc[j][1] + bv1; v01 = v01 > 0.f ? v01 : NEG * v01;
        float v10 = acc[j][2] + bv0; v10 = v10 > 0.f ? v10 : NEG * v10;
        float v11 = acc[j][3] + bv1; v11 = v11 > 0.f ? v11 : NEG * v11;
        acc[j][0] = v00; acc[j][1] = v01; acc[j][2] = v10; acc[j][3] = v11;
        s0 += v00 + v01; q0 += v00 * v00 + v01 * v01;
        s1 += v10 + v11; q1 += v10 * v10 + v11 * v11;
    }
    s0 += __shfl_xor_sync(0xffffffffu, s0, 1); s0 += __shfl_xor_sync(0xffffffffu, s0, 2);
    q0 += __shfl_xor_sync(0xffffffffu, q0, 1); q0 += __shfl_xor_sync(0xffffffffu, q0, 2);
    s1 += __shfl_xor_sync(0xffffffffu, s1, 1); s1 += __shfl_xor_sync(0xffffffffu, s1, 2);
    q1 += __shfl_xor_sync(0xffffffffu, q1, 1); q1 += __shfl_xor_sync(0xffffffffu, q1, 2);
    psum[ch * 128 + r0] = s0; psq[ch * 128 + r0] = q0;
    psum[ch * 128 + r1] = s1; psq[ch * 128 + r1] = q1;
    __syncthreads();
    float st0 = psum[r0] + psum[128 + r0], qt0 = psq[r0] + psq[128 + r0];
    float st1 = psum[r1] + psum[128 + r1], qt1 = psq[r1] + psq[128 + r1];
    float mu0 = st0 * (1.f / 128.f), rs0 = rsqrtf(qt0 * (1.f / 128.f) - mu0 * mu0 + LNEPS);
    float mu1 = st1 * (1.f / 128.f), rs1 = rsqrtf(qt1 * (1.f / 128.f) - mu1 * mu1 + LNEPS);
    #pragma unroll
    for (int j = 0; j < 8; j++) {
        int col = cb + 8 * j + 2 * (lane & 3);
        float g0 = __ldg(&gam[col]), g1 = __ldg(&gam[col + 1]);
        float t0 = __ldg(&bet[col]), t1 = __ldg(&bet[col + 1]);
        split2(Ah, Al, r0 * ASTR + col,
               (acc[j][0] - mu0) * rs0 * g0 + t0, (acc[j][1] - mu0) * rs0 * g1 + t1);
        split2(Ah, Al, r1 * ASTR + col,
               (acc[j][2] - mu1) * rs1 * g0 + t0, (acc[j][3] - mu1) * rs1 * g1 + t1);
    }
}

__device__ __forceinline__ void gates_epi512(float (*acc)[4], const float* __restrict__ bias,
                                             float* stage, int warp, int lane)
{
    const int wr = warp & 7, ch = warp >> 3, cb = ch * 64;
    const int r0 = 16 * wr + (lane >> 2), r1 = r0 + 8;
    #pragma unroll
    for (int j = 0; j < 8; j++) {
        int col = cb + 8 * j + 2 * (lane & 3);
        float bv0 = __ldg(&bias[col]), bv1 = __ldg(&bias[col + 1]);
        *(float2*)&stage[r0 * SSTR + col] = make_float2(acc[j][0] + bv0, acc[j][1] + bv1);
        *(float2*)&stage[r1 * SSTR + col] = make_float2(acc[j][2] + bv0, acc[j][3] + bv1);
    }
}

#define SM_AH   0
#define SM_AL   (128 * ASTR * 2)
#define SM_BH   (2 * 128 * ASTR * 2)
#define SM_BL   (3 * 128 * ASTR * 2)
#define SM_STG  (4 * 128 * ASTR * 2)
#define SM_PS   (SM_STG + 128 * SSTR * 4)
#define SM_TOT  (SM_PS + 4 * 256 * 4)

__global__ void __launch_bounds__(512) ff_kernel(
    const float* __restrict__ x,
    const float* __restrict__ b1, const float* __restrict__ g1, const float* __restrict__ be1,
    const float* __restrict__ b2, const float* __restrict__ g2, const float* __restrict__ be2,
    const float* __restrict__ bih)
{
    extern __shared__ char smem[];
    __nv_bfloat16* Ah = (__nv_bfloat16*)(smem + SM_AH);
    __nv_bfloat16* Al = (__nv_bfloat16*)(smem + SM_AL);
    __nv_bfloat16* Bh = (__nv_bfloat16*)(smem + SM_BH);
    __nv_bfloat16* Bl = (__nv_bfloat16*)(smem + SM_BL);
    float* stage = (float*)(smem + SM_STG);
    float* psum  = (float*)(smem + SM_PS);
    float* psq   = psum + 256;
    const uint32_t a_hi = smem_u32(Ah), a_lo = smem_u32(Al);
    const uint32_t b_hi = smem_u32(Bh), b_lo = smem_u32(Bl);
    const int tid = threadIdx.x, warp = tid >> 5, lane = tid & 31;
    const size_t base = (size_t)blockIdx.x * 128;

    for (int p = tid; p < 128 * 32; p += 512) {
        int row = p >> 5, kp = p & 31;
        float2 v = *(const float2*)&x[(base + row) * IND + 2 * kp];
        split2(Ah, Al, row * ASTR + 2 * kp, v.x, v.y);
    }
    load_wsplit<IND, 512>(g_w1h, g_w1l, Bh, Bl, 128, tid);
    __syncthreads();

    float acc[8][4];
    #pragma unroll
    for (int j = 0; j < 8; j++) { acc[j][0]=acc[j][1]=acc[j][2]=acc[j][3]=0.f; }
    wgemm512<4>(a_hi, a_lo, b_hi, b_lo, acc, warp, lane);
    __syncthreads();
    ln_epi512(acc, b1, g1, be1, Ah, Al, warp, lane, psum, psq);

    load_wsplit<HD, 512>(g_w2h, g_w2l, Bh, Bl, 128, tid);
    __syncthreads();
    #pragma unroll
    for (int j = 0; j < 8; j++) { acc[j][0]=acc[j][1]=acc[j][2]=acc[j][3]=0.f; }
    wgemm512<8>(a_hi, a_lo, b_hi, b_lo, acc, warp, lane);
    __syncthreads();
    ln_epi512(acc, b2, g2, be2, Ah, Al, warp, lane, psum, psq);

    for (int c3 = 0; c3 < 3; c3++) {
        load_wsplit<HD, 512>(g_wih_h + (size_t)c3 * 128 * HD, g_wih_l + (size_t)c3 * 128 * HD,
                             Bh, Bl, 128, tid);
        __syncthreads();
        #pragma unroll
        for (int j = 0; j < 8; j++) { acc[j][0]=acc[j][1]=acc[j][2]=acc[j][3]=0.f; }
        wgemm512<8>(a_hi, a_lo, b_hi, b_lo, acc, warp, lane);
        gates_epi512(acc, bih + c3 * 128, stage, warp, lane);
        __syncthreads();
        float* gout = g_gates + base * G3 + c3 * 128;
        for (int it = tid; it < 128 * 128; it += 512) {
            int r = it >> 7, cc = it & 127;
            gout[(size_t)r * G3 + cc] = stage[r * SSTR + cc];
        }
        __syncthreads();
    }
}

// ============================== REC v5 (R12, unchanged): cluster-2 j-split + k-split ==============================
#define RSM_WH  0
#define RSM_WL  49152
#define RSM_A   98304
#define RSM_P   (RSM_A + 16384)
#define RSM_MB  (RSM_P + 12288)
#define RSM_TOT (RSM_MB + 16)

__device__ __forceinline__ float sigf(float x) {
    float e = __expf(-x);
    return __fdividef(1.f, 1.f + e);
}
__device__ __forceinline__ float tanhf_fast(float x) {
    return fmaf(2.f, sigf(2.f * x), -1.f);
}

#define MBAR_INIT(m, n)  asm volatile("mbarrier.init.shared.b64 [%0], %1;" :: "r"(m), "r"(n) : "memory")
#define MBAR_ARRIVE_LOCAL(m) \
    asm volatile("mbarrier.arrive.release.cluster.shared::cta.b64 _, [%0];" :: "r"(m) : "memory")
#define MBAR_ARRIVE_REMOTE(m) \
    asm volatile("mbarrier.arrive.release.cluster.shared::cluster.b64 _, [%0];" :: "r"(m) : "memory")
#define MBAR_WAIT_CL(mb, ph) do {                                              \
    uint32_t _m = (mb); uint32_t _p = (ph); uint32_t _d;                       \
    asm volatile("{\n\t.reg .pred p;\n\t"                                      \
        "mbarrier.try_wait.parity.acquire.cluster.shared::cta.b64 p, [%1], %2;\n\t" \
        "selp.b32 %0, 1, 0, p;\n\t}"                                           \
        : "=r"(_d) : "r"(_m), "r"(_p) : "memory");                             \
    if (!_d) {                                                                 \
        asm volatile("{\n\t.reg .pred P1;\n\t"                                 \
            "W_%=:\n\t"                                                        \
            "mbarrier.try_wait.parity.acquire.cluster.shared::cta.b64 P1, [%0], %1, 0x989680;\n\t" \
            "@P1 bra.uni D_%=;\n\tbra.uni W_%=;\n\tD_%=:\n\t}"                 \
            :: "r"(_m), "r"(_p) : "memory");                                   \
    }                                                                          \
} while (0)

__device__ __forceinline__ void stA2_both(char* AHl, uint32_t AHp, int b, int j, float2 h) {
    uint32_t off = (uint32_t)(b * 256 + (((j >> 3) ^ (b & 7)) << 4) + (j & 7) * 2);
    __nv_bfloat16 h0 = __float2bfloat16(h.x), h1 = __float2bfloat16(h.y);
    __nv_bfloat16 l0 = __float2bfloat16(h.x - __bfloat162float(h0));
    __nv_bfloat16 l1 = __float2bfloat16(h.y - __bfloat162float(h1));
    __nv_bfloat162 hh; hh.x = h0; hh.y = h1;
    __nv_bfloat162 ll; ll.x = l0; ll.y = l1;
    uint32_t hw = *(uint32_t*)&hh, lw = *(uint32_t*)&ll;
    *(uint32_t*)(AHl + off) = hw;
    *(uint32_t*)(AHl + 4096 + off) = lw;
    asm volatile("st.shared::cluster.u32 [%0], %1;" :: "r"(AHp + off), "r"(hw) : "memory");
    asm volatile("st.shared::cluster.u32 [%0], %1;" :: "r"(AHp + 4096 + off), "r"(lw) : "memory");
}

__global__ void __launch_bounds__(512, 1) __cluster_dims__(2, 1, 1)
rec_kernel(
    const float* __restrict__ hx, const float* __restrict__ Whh,
    const float* __restrict__ bhh, const void* __restrict__ isinit,
    float* __restrict__ hxout)
{
    extern __shared__ char sm[];
    char* WH = sm + RSM_WH;
    char* WL = sm + RSM_WL;
    const uint32_t whb = smem_u32(WH), wlb = smem_u32(WL);
    const uint32_t aab = smem_u32(sm + RSM_A);
    const uint32_t mbar = smem_u32(sm + RSM_MB);
    float* Pbuf = (float*)(sm + RSM_P);
    const int tid = threadIdx.x, warp = tid >> 5, lane = tid & 31;
    const int wr = warp & 7, kh = warp >> 3;

    uint32_t rank;
    asm("mov.u32 %0, %%cluster_ctarank;" : "=r"(rank));
    const uint32_t peer = rank ^ 1u;
    const int b0 = (blockIdx.x >> 1) * 16;
    const int jhalf = (int)rank * 64;

    uint32_t aab_peer, mbar_peer;
    asm("mapa.shared::cluster.u32 %0, %1, %2;" : "=r"(aab_peer)  : "r"(aab),  "r"(peer));
    asm("mapa.shared::cluster.u32 %0, %1, %2;" : "=r"(mbar_peer) : "r"(mbar), "r"(peer));

    if (tid == 0) MBAR_INIT(mbar, 2);

    for (int p = tid; p < 192 * 64; p += 512) {
        int row_local = p >> 6, kp = p & 63, k = 2 * kp;
        int g = row_local >> 6, jn = row_local & 63;
        int grow = (g << 7) + jhalf + jn;
        float2 v = *(const float2*)&Whh[grow * 128 + k];
        uint32_t off = (uint32_t)(row_local * 256 + (((k >> 3) ^ (row_local & 7)) << 4) + (k & 7) * 2);
        split2((__nv_bfloat16*)(WH + off), (__nv_bfloat16*)(WL + off), 0, v.x, v.y);
    }

    const int b = (lane >> 2) + 8 * kh;
    const int j_g = jhalf + 8 * wr + 2 * (lane & 3);

    float bv[3][2];
    #pragma unroll
    for (int g = 0; g < 3; g++) {
        int col = g * 128 + j_g;
        bv[g][0] = __ldg(&bhh[col]);
        bv[g][1] = __ldg(&bhh[col + 1]);
    }

    const int wm = g_wordmode;
    const unsigned int*  ii32 = (const unsigned int*)isinit;
    const unsigned char* ii8  = (const unsigned char*)isinit;

    float hprev[2];
    float gxc[3][2];
    {
        char* AH0 = sm + RSM_A;
        size_t ib = (size_t)(b0 + b) * T_;
        int f0 = wm ? (ii32[ib] != 0u) : (ii8[ib] != 0);
        float2 v = *(const float2*)&hx[(size_t)(b0 + b) * HD + j_g];
        if (f0) { v.x = 0.f; v.y = 0.f; }
        hprev[0] = v.x; hprev[1] = v.y;
        stA2_both(AH0, aab_peer, b, j_g, v);
        #pragma unroll
        for (int g = 0; g < 3; g++) {
            float2 gv = *(const float2*)&g_gates[ib * G3 + g * 128 + j_g];
            gxc[g][0] = gv.x; gxc[g][1] = gv.y;
        }
    }

    asm volatile("barrier.cluster.arrive.aligned;" ::: "memory");
    asm volatile("barrier.cluster.wait.aligned;" ::: "memory");

    const int arow = lane & 15;
    const uint32_t abase = (uint32_t)(arow * 256);
    const int achx = (lane & 16) ? 1 : 0, arx = arow & 7;
    const int nrl = 8 * wr + (lane & 7);
    const int kc = lane >> 3;

    const int pub_slot  = ((kh * 8 + wr) * 32 + lane) * 6;
    const int read_slot = (((1 - kh) * 8 + wr) * 32 + lane) * 6;

    int cur = 0;
    for (int t = 0; t < T_; t++) {
        float ngx[3][2];
        int nf = 0;
        if (t + 1 < T_) {
            size_t ib = (size_t)(b0 + b) * T_ + (t + 1);
            nf = wm ? (ii32[ib] != 0u) : (ii8[ib] != 0);
            #pragma unroll
            for (int g = 0; g < 3; g++) {
                float2 gv = *(const float2*)&g_gates[ib * G3 + g * 128 + j_g];
                ngx[g][0] = gv.x; ngx[g][1] = gv.y;
            }
        }

        float acc[3][4];
        #pragma unroll
        for (int g = 0; g < 3; g++) { acc[g][0]=acc[g][1]=acc[g][2]=acc[g][3]=0.f; }
        const uint32_t ahb = aab + (uint32_t)cur * 8192;
        const uint32_t alb = ahb + 4096;
        #pragma unroll
        for (int kkl = 0; kkl < 2; kkl++) {
            const int kk = 2 * kh + kkl;
            uint32_t ah4[2][4], al4[2][4];
            #pragma unroll
            for (int s = 0; s < 2; s++) {
                int k0 = 2 * kk + s;
                uint32_t ach = (uint32_t)((2 * k0 + achx) ^ arx);
                ldsm_x4(ah4[s], ahb + abase + (ach << 4));
                ldsm_x4(al4[s], alb + abase + (ach << 4));
            }
            #pragma unroll
            for (int g = 0; g < 3; g++) {
                int row_local = (g << 6) + nrl;
                uint32_t chunk = (uint32_t)((4 * kk + kc) ^ (lane & 7));
                uint32_t boff = (uint32_t)(row_local * 256) + (chunk << 4);
                uint32_t bh4[4], bl4[4];
                ldsm_x4(bh4, whb + boff);
                ldsm_x4(bl4, wlb + boff);
                #pragma unroll
                for (int s = 0; s < 2; s++) {
                    mma16816(acc[g], ah4[s], bh4 + 2 * s);
                    mma16816(acc[g], ah4[s], bl4 + 2 * s);
                    mma16816(acc[g], al4[s], bh4 + 2 * s);
                }
            }
        }

        {
            const int pix = 2 * (1 - kh);
            #pragma unroll
            for (int g = 0; g < 3; g++) {
                Pbuf[pub_slot + 2 * g]     = acc[g][pix];
                Pbuf[pub_slot + 2 * g + 1] = acc[g][pix + 1];
            }
        }
        __syncthreads();

        const int nxt = cur ^ 1;
        char* AHn = sm + RSM_A + nxt * 8192;
        uint32_t pAHn = aab_peer + (uint32_t)nxt * 8192;
        float hn_[2];
        #pragma unroll
        for (int q = 0; q < 2; q++) {
            const int ix = 2 * kh + q;
            float a0 = acc[0][ix] + Pbuf[read_slot + 0 + q] + bv[0][q];
            float a1 = acc[1][ix] + Pbuf[read_slot + 2 + q] + bv[1][q];
            float a2 = acc[2][ix] + Pbuf[read_slot + 4 + q] + bv[2][q];
            float rr = sigf(gxc[0][q] + a0);
            float zz = sigf(gxc[1][q] + a1);
            float nn = tanhf_fast(gxc[2][q] + rr * a2);
            hn_[q] = (1.f - zz) * nn + zz * hprev[q];
        }
        *(float2*)&g_y[((size_t)(b0 + b) * T_ + t) * HD + j_g] = make_float2(hn_[0], hn_[1]);
        if (t + 1 < T_) {
            float2 he = nf ? make_float2(0.f, 0.f) : make_float2(hn_[0], hn_[1]);
            hprev[0] = he.x; hprev[1] = he.y;
            stA2_both(AHn, pAHn, b, j_g, he);
            #pragma unroll
            for (int g = 0; g < 3; g++) { gxc[g][0] = ngx[g][0]; gxc[g][1] = ngx[g][1]; }

            __syncthreads();
            if (tid == 0) {
                MBAR_ARRIVE_LOCAL(mbar);
                MBAR_ARRIVE_REMOTE(mbar_peer);
            }
            MBAR_WAIT_CL(mbar, (uint32_t)(t & 1));
        } else {
            *(float2*)&hxout[(size_t)(b0 + b) * HD + j_g] = make_float2(hn_[0], hn_[1]);
        }
        cur = nxt;
    }
}

// ---------------- out: 256 threads (R9/R12 structure, pre-split Wout) ----------------
#define OSM_AH  0
#define OSM_AL  (128 * ASTR * 2)
#define OSM_BH  (2 * 128 * ASTR * 2)
#define OSM_BL  (OSM_BH + 64 * ASTR * 2)
#define OSM_TOT (OSM_BH + 2 * 64 * ASTR * 2)

__global__ void __launch_bounds__(256, 2) out_kernel(
    const float* __restrict__ bout, float* __restrict__ out)
{
    extern __shared__ char smem[];
    __nv_bfloat16* Ah = (__nv_bfloat16*)(smem + OSM_AH);
    __nv_bfloat16* Al = (__nv_bfloat16*)(smem + OSM_AL);
    __nv_bfloat16* Bh = (__nv_bfloat16*)(smem + OSM_BH);
    __nv_bfloat16* Bl = (__nv_bfloat16*)(smem + OSM_BL);
    const uint32_t a_hi = smem_u32(Ah), a_lo = smem_u32(Al);
    const uint32_t b_hi = smem_u32(Bh), b_lo = smem_u32(Bl);
    const int tid = threadIdx.x, warp = tid >> 5, lane = tid & 31;
    const size_t base = (size_t)blockIdx.x * 128;

    for (int p = tid; p < 128 * 64; p += 256) {
        int row = p >> 6, kp = p & 63;
        float2 v = *(const float2*)&g_y[(base + row) * HD + 2 * kp];
        split2(Ah, Al, row * ASTR + 2 * kp, v.x, v.y);
    }
    load_wsplit<HD, 256>(g_wo_h, g_wo_l, Bh, Bl, 64, tid);
    __syncthreads();

    float acc[8][4];
    #pragma unroll
    for (int j = 0; j < 8; j++) { acc[j][0]=acc[j][1]=acc[j][2]=acc[j][3]=0.f; }

    const int arow = 16 * warp + (lane & 7) + ((lane & 8) ? 8 : 0);
    const int acg  = (lane & 16) ? 8 : 0;
    const uint32_t aoff = (uint32_t)(arow * ASTR + acg) * 2;
    const int nloc = (lane & 7) + ((lane & 16) ? 8 : 0);
    const int bkg  = (lane & 8) ? 8 : 0;
    const uint32_t boff = (uint32_t)(nloc * ASTR + bkg) * 2;
    #pragma unroll
    for (int k0 = 0; k0 < 8; k0++) {
        uint32_t ah[4], al[4];
        ldsm_x4(ah, a_hi + aoff + k0 * 32);
        ldsm_x4(al, a_lo + aoff + k0 * 32);
        #pragma unroll
        for (int jp = 0; jp < 4; jp++) {
            uint32_t bo = boff + (uint32_t)(jp * 16 * ASTR) * 2 + k0 * 32;
            uint32_t bh[4], bl[4];
            ldsm_x4(bh, b_hi + bo);
            ldsm_x4(bl, b_lo + bo);
            mma16816(acc[2*jp],     ah, bh);
            mma16816(acc[2*jp],     ah, bl);
            mma16816(acc[2*jp],     al, bh);
            mma16816(acc[2*jp + 1], ah, bh + 2);
            mma16816(acc[2*jp + 1], ah, bl + 2);
            mma16816(acc[2*jp + 1], al, bh + 2);
        }
    }

    const int r0 = 16 * warp + (lane >> 2), r1 = r0 + 8;
    #pragma unroll
    for (int j = 0; j < 8; j++) {
        int col = 8 * j + 2 * (lane & 3);
        float bv0 = __ldg(&bout[col]), bv1 = __ldg(&bout[col + 1]);
        *(float2*)&out[(base + r0) * OD + col] = make_float2(acc[j][0] + bv0, acc[j][1] + bv1);
        *(float2*)&out[(base + r1) * OD + col] = make_float2(acc[j][2] + bv0, acc[j][3] + bv1);
    }
}

// ---------------- launcher ----------------
extern "C" void kernel_launch(void* const* d_in, const int* in_sizes, int n_in,
                              void* d_out, int out_size)
{
    const float* x    = (const float*)d_in[0];
    const void*  isin = d_in[1];
    const float* hx   = (const float*)d_in[2];
    const float* W1   = (const float*)d_in[3];
    const float* b1   = (const float*)d_in[4];
    const float* g1   = (const float*)d_in[5];
    const float* be1  = (const float*)d_in[6];
    const float* W2   = (const float*)d_in[7];
    const float* b2   = (const float*)d_in[8];
    const float* g2   = (const float*)d_in[9];
    const float* be2  = (const float*)d_in[10];
    const float* Wih  = (const float*)d_in[11];
    const float* Whh  = (const float*)d_in[12];
    const float* bih  = (const float*)d_in[13];
    const float* bhh  = (const float*)d_in[14];
    const float* Wout = (const float*)d_in[15];
    const float* bout = (const float*)d_in[16];
    float* out = (float*)d_out;

    cudaFuncSetAttribute(ff_kernel,  cudaFuncAttributeMaxDynamicSharedMemorySize, SM_TOT);
    cudaFuncSetAttribute(rec_kernel, cudaFuncAttributeMaxDynamicSharedMemorySize, RSM_TOT);
    cudaFuncSetAttribute(out_kernel, cudaFuncAttributeMaxDynamicSharedMemorySize, OSM_TOT);

    detect_kernel<<<1, 256>>>((const unsigned int*)isin);
    prep_kernel<<<160, 512>>>(W1, W2, Wih, Wout);
    ff_kernel<<<BT_ / 128, 512, SM_TOT>>>(x, b1, g1, be1, b2, g2, be2, bih);
    rec_kernel<<<128, 512, RSM_TOT>>>(hx, Whh, bhh, isin, out + (size_t)BT_ * OD);
    out_kernel<<<BT_ / 128, 256, OSM_TOT>>>(bout, out);
}

// round 15
// speedup vs baseline: 1.1524x; 1.0580x over previous
#include <cuda_runtime.h>
#include <cuda_bf16.h>
#include <math.h>
#include <stdint.h>

#define B_    1024
#define T_    512
#define BT_   (B_*T_)
#define IND   64
#define HD    128
#define G3    384
#define OD    64
#define NEG   0.01f
#define LNEPS 1e-5f

#define ASTR  136
#define SSTR  132

// ---------------- scratch ----------------
static __device__ float g_gates[(size_t)BT_ * G3];   // [B*T, 384]
static __device__ float g_y[(size_t)BT_ * HD];       // [B*T, 128]
static __device__ int   g_wordmode;

// pre-split bf16 weight planes
static __device__ __align__(16) __nv_bfloat16 g_w1h[HD * IND],  g_w1l[HD * IND];
static __device__ __align__(16) __nv_bfloat16 g_w2h[HD * HD],   g_w2l[HD * HD];
static __device__ __align__(16) __nv_bfloat16 g_wih_h[G3 * HD], g_wih_l[G3 * HD];
static __device__ __align__(16) __nv_bfloat16 g_wo_h[OD * HD],  g_wo_l[OD * HD];

__global__ void detect_kernel(const unsigned int* __restrict__ p) {
    __shared__ int bad;
    if (threadIdx.x == 0) bad = 0;
    __syncthreads();
    unsigned v = p[threadIdx.x];
    if (v != 0u && v != 1u && v != 0x3F800000u) atomicExch(&bad, 1);
    __syncthreads();
    if (threadIdx.x == 0) g_wordmode = bad ? 0 : 1;
}

__device__ __forceinline__ void splitw1(float v, __nv_bfloat16* h, __nv_bfloat16* l, int i) {
    __nv_bfloat16 hh = __float2bfloat16(v);
    h[i] = hh;
    l[i] = __float2bfloat16(v - __bfloat162float(hh));
}

__global__ void prep_kernel(const float* __restrict__ W1, const float* __restrict__ W2,
                            const float* __restrict__ Wih, const float* __restrict__ Wout)
{
    int idx = blockIdx.x * blockDim.x + threadIdx.x;
    if (idx < 8192)                splitw1(W1[idx], g_w1h, g_w1l, idx);
    else if (idx < 24576)          { int i = idx - 8192;  splitw1(W2[i],  g_w2h,  g_w2l,  i); }
    else if (idx < 73728)          { int i = idx - 24576; splitw1(Wih[i], g_wih_h, g_wih_l, i); }
    else if (idx < 81920)          { int i = idx - 73728; splitw1(Wout[i], g_wo_h, g_wo_l, i); }
}

// ---------------- mma.sync helpers ----------------
__device__ __forceinline__ uint32_t smem_u32(const void* p) {
    uint32_t a;
    asm("{ .reg .u64 t; cvta.to.shared.u64 t, %1; cvt.u32.u64 %0, t; }" : "=r"(a) : "l"(p));
    return a;
}
__device__ __forceinline__ void ldsm_x4(uint32_t* r, uint32_t addr) {
    asm volatile("ldmatrix.sync.aligned.m8n8.x4.shared.b16 {%0,%1,%2,%3}, [%4];"
                 : "=r"(r[0]), "=r"(r[1]), "=r"(r[2]), "=r"(r[3]) : "r"(addr));
}
__device__ __forceinline__ void mma16816(float* d, const uint32_t* a, const uint32_t* b) {
    asm volatile("mma.sync.aligned.m16n8k16.row.col.f32.bf16.bf16.f32 "
                 "{%0,%1,%2,%3}, {%4,%5,%6,%7}, {%8,%9}, {%0,%1,%2,%3};"
                 : "+f"(d[0]), "+f"(d[1]), "+f"(d[2]), "+f"(d[3])
                 : "r"(a[0]), "r"(a[1]), "r"(a[2]), "r"(a[3]), "r"(b[0]), "r"(b[1]));
}

__device__ __forceinline__ void split2(__nv_bfloat16* hi, __nv_bfloat16* lo, int eo,
                                       float a, float b) {
    __nv_bfloat16 h0 = __float2bfloat16(a), h1 = __float2bfloat16(b);
    __nv_bfloat16 l0 = __float2bfloat16(a - __bfloat162float(h0));
    __nv_bfloat16 l1 = __float2bfloat16(b - __bfloat162float(h1));
    __nv_bfloat162 hh; hh.x = h0; hh.y = h1;
    __nv_bfloat162 ll; ll.x = l0; ll.y = l1;
    *(__nv_bfloat162*)(hi + eo) = hh;
    *(__nv_bfloat162*)(lo + eo) = ll;
}

template<int K, int NT>
__device__ __forceinline__ void load_wsplit(const __nv_bfloat16* __restrict__ gh,
                                            const __nv_bfloat16* __restrict__ gl,
                                            __nv_bfloat16* bh, __nv_bfloat16* bl,
                                            int rows, int tid)
{
    const int chunks = rows * (K / 8);
    for (int p = tid; p < chunks; p += NT) {
        int row = p / (K / 8), c = p % (K / 8);
        *(uint4*)(bh + row * ASTR + c * 8) = *(const uint4*)(gh + row * K + c * 8);
        *(uint4*)(bl + row * ASTR + c * 8) = *(const uint4*)(gl + row * K + c * 8);
    }
}

// ============================== FF: 512 threads, 16 warps (R14, unchanged) ==============================
template<int NK>
__device__ __forceinline__ void wgemm512(uint32_t a_hi, uint32_t a_lo,
                                         uint32_t b_hi, uint32_t b_lo,
                                         float (*acc)[4], int warp, int lane)
{
    const int wr = warp & 7, ch = warp >> 3;
    const int arow = 16 * wr + (lane & 7) + ((lane & 8) ? 8 : 0);
    const int acg  = (lane & 16) ? 8 : 0;
    const uint32_t aoff = (uint32_t)(arow * ASTR + acg) * 2;
    const int nloc = ch * 64 + (lane & 7) + ((lane & 16) ? 8 : 0);
    const int bkg  = (lane & 8) ? 8 : 0;
    const uint32_t boff = (uint32_t)(nloc * ASTR + bkg) * 2;
    #pragma unroll
    for (int k0 = 0; k0 < NK; k0++) {
        uint32_t ah[4], al[4];
        ldsm_x4(ah, a_hi + aoff + k0 * 32);
        ldsm_x4(al, a_lo + aoff + k0 * 32);
        #pragma unroll
        for (int jp = 0; jp < 4; jp++) {
            uint32_t bo = boff + (uint32_t)(jp * 16 * ASTR) * 2 + k0 * 32;
            uint32_t bh[4], bl[4];
            ldsm_x4(bh, b_hi + bo);
            ldsm_x4(bl, b_lo + bo);
            mma16816(acc[2*jp],     ah, bh);
            mma16816(acc[2*jp],     ah, bl);
            mma16816(acc[2*jp],     al, bh);
            mma16816(acc[2*jp + 1], ah, bh + 2);
            mma16816(acc[2*jp + 1], ah, bl + 2);
            mma16816(acc[2*jp + 1], al, bh + 2);
        }
    }
}

__device__ __forceinline__ void ln_epi512(float (*acc)[4],
    const float* __restrict__ bias, const float* __restrict__ gam, const float* __restrict__ bet,
    __nv_bfloat16* Ah, __nv_bfloat16* Al, int warp, int lane,
    float* psum, float* psq)
{
    const int wr = warp & 7, ch = warp >> 3, cb = ch * 64;
    const int r0 = 16 * wr + (lane >> 2), r1 = r0 + 8;
    float s0 = 0.f, q0 = 0.f, s1 = 0.f, q1 = 0.f;
    #pragma unroll
    for (int j = 0; j < 8; j++) {
        int col = cb + 8 * j + 2 * (lane & 3);
        float bv0 = __ldg(&bias[col]), bv1 = __ldg(&bias[col + 1]);
        float v00 = acc[j][0] + bv0; v00 = v00 > 0.f ? v00 : NEG * v00;
        float v01 = acc[j][1] + bv1; v01 = v01 > 0.f ? v01 : NEG * v01;
        float v10 = acc[j][2] + bv0; v10 = v10 > 0.f ? v10 : NEG * v10;
        float v11 = acc[j][3] + bv1; v11 = v11 > 0.f ? v11 : NEG * v11;
        acc[j][0] = v00; acc[j][1] = v01; acc[j][2] = v10; acc[j][3] = v11;
        s0 += v00 + v01; q0 += v00 * v00 + v01 * v01;
        s1 += v10 + v11; q1 += v10 * v10 + v11 * v11;
    }
    s0 += __shfl_xor_sync(0xffffffffu, s0, 1); s0 += __shfl_xor_sync(0xffffffffu, s0, 2);
    q0 += __shfl_xor_sync(0xffffffffu, q0, 1); q0 += __shfl_xor_sync(0xffffffffu, q0, 2);
    s1 += __shfl_xor_sync(0xffffffffu, s1, 1); s1 += __shfl_xor_sync(0xffffffffu, s1, 2);
    q1 += __shfl_xor_sync(0xffffffffu, q1, 1); q1 += __shfl_xor_sync(0xffffffffu, q1, 2);
    psum[ch * 128 + r0] = s0; psq[ch * 128 + r0] = q0;
    psum[ch * 128 + r1] = s1; psq[ch * 128 + r1] = q1;
    __syncthreads();
    float st0 = psum[r0] + psum[128 + r0], qt0 = psq[r0] + psq[128 + r0];
    float st1 = psum[r1] + psum[128 + r1], qt1 = psq[r1] + psq[128 + r1];
    float mu0 = st0 * (1.f / 128.f), rs0 = rsqrtf(qt0 * (1.f / 128.f) - mu0 * mu0 + LNEPS);
    float mu1 = st1 * (1.f / 128.f), rs1 = rsqrtf(qt1 * (1.f / 128.f) - mu1 * mu1 + LNEPS);
    #pragma unroll
    for (int j = 0; j < 8; j++) {
        int col = cb + 8 * j + 2 * (lane & 3);
        float g0 = __ldg(&gam[col]), g1 = __ldg(&gam[col + 1]);
        float t0 = __ldg(&bet[col]), t1 = __ldg(&bet[col + 1]);
        split2(Ah, Al, r0 * ASTR + col,
               (acc[j][0] - mu0) * rs0 * g0 + t0, (acc[j][1] - mu0) * rs0 * g1 + t1);
        split2(Ah, Al, r1 * ASTR + col,
               (acc[j][2] - mu1) * rs1 * g0 + t0, (acc[j][3] - mu1) * rs1 * g1 + t1);
    }
}

__device__ __forceinline__ void gates_epi512(float (*acc)[4], const float* __restrict__ bias,
                                             float* stage, int warp, int lane)
{
    const int wr = warp & 7, ch = warp >> 3, cb = ch * 64;
    const int r0 = 16 * wr + (lane >> 2), r1 = r0 + 8;
    #pragma unroll
    for (int j = 0; j < 8; j++) {
        int col = cb + 8 * j + 2 * (lane & 3);
        float bv0 = __ldg(&bias[col]), bv1 = __ldg(&bias[col + 1]);
        *(float2*)&stage[r0 * SSTR + col] = make_float2(acc[j][0] + bv0, acc[j][1] + bv1);
        *(float2*)&stage[r1 * SSTR + col] = make_float2(acc[j][2] + bv0, acc[j][3] + bv1);
    }
}

#define SM_AH   0
#define SM_AL   (128 * ASTR * 2)
#define SM_BH   (2 * 128 * ASTR * 2)
#define SM_BL   (3 * 128 * ASTR * 2)
#define SM_STG  (4 * 128 * ASTR * 2)
#define SM_PS   (SM_STG + 128 * SSTR * 4)
#define SM_TOT  (SM_PS + 4 * 256 * 4)

__global__ void __launch_bounds__(512) ff_kernel(
    const float* __restrict__ x,
    const float* __restrict__ b1, const float* __restrict__ g1, const float* __restrict__ be1,
    const float* __restrict__ b2, const float* __restrict__ g2, const float* __restrict__ be2,
    const float* __restrict__ bih)
{
    extern __shared__ char smem[];
    __nv_bfloat16* Ah = (__nv_bfloat16*)(smem + SM_AH);
    __nv_bfloat16* Al = (__nv_bfloat16*)(smem + SM_AL);
    __nv_bfloat16* Bh = (__nv_bfloat16*)(smem + SM_BH);
    __nv_bfloat16* Bl = (__nv_bfloat16*)(smem + SM_BL);
    float* stage = (float*)(smem + SM_STG);
    float* psum  = (float*)(smem + SM_PS);
    float* psq   = psum + 256;
    const uint32_t a_hi = smem_u32(Ah), a_lo = smem_u32(Al);
    const uint32_t b_hi = smem_u32(Bh), b_lo = smem_u32(Bl);
    const int tid = threadIdx.x, warp = tid >> 5, lane = tid & 31;
    const size_t base = (size_t)blockIdx.x * 128;

    for (int p = tid; p < 128 * 32; p += 512) {
        int row = p >> 5, kp = p & 31;
        float2 v = *(const float2*)&x[(base + row) * IND + 2 * kp];
        split2(Ah, Al, row * ASTR + 2 * kp, v.x, v.y);
    }
    load_wsplit<IND, 512>(g_w1h, g_w1l, Bh, Bl, 128, tid);
    __syncthreads();

    float acc[8][4];
    #pragma unroll
    for (int j = 0; j < 8; j++) { acc[j][0]=acc[j][1]=acc[j][2]=acc[j][3]=0.f; }
    wgemm512<4>(a_hi, a_lo, b_hi, b_lo, acc, warp, lane);
    __syncthreads();
    ln_epi512(acc, b1, g1, be1, Ah, Al, warp, lane, psum, psq);

    load_wsplit<HD, 512>(g_w2h, g_w2l, Bh, Bl, 128, tid);
    __syncthreads();
    #pragma unroll
    for (int j = 0; j < 8; j++) { acc[j][0]=acc[j][1]=acc[j][2]=acc[j][3]=0.f; }
    wgemm512<8>(a_hi, a_lo, b_hi, b_lo, acc, warp, lane);
    __syncthreads();
    ln_epi512(acc, b2, g2, be2, Ah, Al, warp, lane, psum, psq);

    for (int c3 = 0; c3 < 3; c3++) {
        load_wsplit<HD, 512>(g_wih_h + (size_t)c3 * 128 * HD, g_wih_l + (size_t)c3 * 128 * HD,
                             Bh, Bl, 128, tid);
        __syncthreads();
        #pragma unroll
        for (int j = 0; j < 8; j++) { acc[j][0]=acc[j][1]=acc[j][2]=acc[j][3]=0.f; }
        wgemm512<8>(a_hi, a_lo, b_hi, b_lo, acc, warp, lane);
        gates_epi512(acc, bih + c3 * 128, stage, warp, lane);
        __syncthreads();
        float* gout = g_gates + base * G3 + c3 * 128;
        for (int it = tid; it < 128 * 128; it += 512) {
            int r = it >> 7, cc = it & 127;
            gout[(size_t)r * G3 + cc] = stage[r * SSTR + cc];
        }
        __syncthreads();
    }
}

// ============================== REC v7: hoisted W fragments + repositioned wait ==============================
#define RSM_WH  0
#define RSM_WL  49152
#define RSM_A   98304
#define RSM_P   (RSM_A + 16384)
#define RSM_MB  (RSM_P + 12288)
#define RSM_TOT (RSM_MB + 16)

__device__ __forceinline__ float sigf(float x) {
    float e = __expf(-x);
    return __fdividef(1.f, 1.f + e);
}
__device__ __forceinline__ float tanhf_fast(float x) {
    return fmaf(2.f, sigf(2.f * x), -1.f);
}

#define MBAR_INIT(m, n)  asm volatile("mbarrier.init.shared.b64 [%0], %1;" :: "r"(m), "r"(n) : "memory")
#define MBAR_ARRIVE_LOCAL(m) \
    asm volatile("mbarrier.arrive.release.cluster.shared::cta.b64 _, [%0];" :: "r"(m) : "memory")
#define MBAR_ARRIVE_REMOTE(m) \
    asm volatile("mbarrier.arrive.release.cluster.shared::cluster.b64 _, [%0];" :: "r"(m) : "memory")
#define MBAR_WAIT_CL(mb, ph) do {                                              \
    uint32_t _m = (mb); uint32_t _p = (ph); uint32_t _d;                       \
    asm volatile("{\n\t.reg .pred p;\n\t"                                      \
        "mbarrier.try_wait.parity.acquire.cluster.shared::cta.b64 p, [%1], %2;\n\t" \
        "selp.b32 %0, 1, 0, p;\n\t}"                                           \
        : "=r"(_d) : "r"(_m), "r"(_p) : "memory");                             \
    if (!_d) {                                                                 \
        asm volatile("{\n\t.reg .pred P1;\n\t"                                 \
            "W_%=:\n\t"                                                        \
            "mbarrier.try_wait.parity.acquire.cluster.shared::cta.b64 P1, [%0], %1, 0x989680;\n\t" \
            "@P1 bra.uni D_%=;\n\tbra.uni W_%=;\n\tD_%=:\n\t}"                 \
            :: "r"(_m), "r"(_p) : "memory");                                   \
    }                                                                          \
} while (0)

__device__ __forceinline__ void stA2_both(char* AHl, uint32_t AHp, int b, int j, float2 h) {
    uint32_t off = (uint32_t)(b * 256 + (((j >> 3) ^ (b & 7)) << 4) + (j & 7) * 2);
    __nv_bfloat16 h0 = __float2bfloat16(h.x), h1 = __float2bfloat16(h.y);
    __nv_bfloat16 l0 = __float2bfloat16(h.x - __bfloat162float(h0));
    __nv_bfloat16 l1 = __float2bfloat16(h.y - __bfloat162float(h1));
    __nv_bfloat162 hh; hh.x = h0; hh.y = h1;
    __nv_bfloat162 ll; ll.x = l0; ll.y = l1;
    uint32_t hw = *(uint32_t*)&hh, lw = *(uint32_t*)&ll;
    *(uint32_t*)(AHl + off) = hw;
    *(uint32_t*)(AHl + 4096 + off) = lw;
    asm volatile("st.shared::cluster.u32 [%0], %1;" :: "r"(AHp + off), "r"(hw) : "memory");
    asm volatile("st.shared::cluster.u32 [%0], %1;" :: "r"(AHp + 4096 + off), "r"(lw) : "memory");
}

__global__ void __launch_bounds__(512, 1) __cluster_dims__(2, 1, 1)
rec_kernel(
    const float* __restrict__ hx, const float* __restrict__ Whh,
    const float* __restrict__ bhh, const void* __restrict__ isinit,
    float* __restrict__ hxout)
{
    extern __shared__ char sm[];
    char* WH = sm + RSM_WH;
    char* WL = sm + RSM_WL;
    const uint32_t whb = smem_u32(WH), wlb = smem_u32(WL);
    const uint32_t aab = smem_u32(sm + RSM_A);
    const uint32_t mbar = smem_u32(sm + RSM_MB);
    float* Pbuf = (float*)(sm + RSM_P);
    const int tid = threadIdx.x, warp = tid >> 5, lane = tid & 31;
    const int wr = warp & 7, kh = warp >> 3;

    uint32_t rank;
    asm("mov.u32 %0, %%cluster_ctarank;" : "=r"(rank));
    const uint32_t peer = rank ^ 1u;
    const int b0 = (blockIdx.x >> 1) * 16;
    const int jhalf = (int)rank * 64;

    uint32_t aab_peer, mbar_peer;
    asm("mapa.shared::cluster.u32 %0, %1, %2;" : "=r"(aab_peer)  : "r"(aab),  "r"(peer));
    asm("mapa.shared::cluster.u32 %0, %1, %2;" : "=r"(mbar_peer) : "r"(mbar), "r"(peer));

    if (tid == 0) MBAR_INIT(mbar, 2);

    for (int p = tid; p < 192 * 64; p += 512) {
        int row_local = p >> 6, kp = p & 63, k = 2 * kp;
        int g = row_local >> 6, jn = row_local & 63;
        int grow = (g << 7) + jhalf + jn;
        float2 v = *(const float2*)&Whh[grow * 128 + k];
        uint32_t off = (uint32_t)(row_local * 256 + (((k >> 3) ^ (row_local & 7)) << 4) + (k & 7) * 2);
        split2((__nv_bfloat16*)(WH + off), (__nv_bfloat16*)(WL + off), 0, v.x, v.y);
    }

    const int b = (lane >> 2) + 8 * kh;
    const int j_g = jhalf + 8 * wr + 2 * (lane & 3);

    float bv[3][2];
    #pragma unroll
    for (int g = 0; g < 3; g++) {
        int col = g * 128 + j_g;
        bv[g][0] = __ldg(&bhh[col]);
        bv[g][1] = __ldg(&bhh[col + 1]);
    }

    const int wm = g_wordmode;
    const unsigned int*  ii32 = (const unsigned int*)isinit;
    const unsigned char* ii8  = (const unsigned char*)isinit;

    float hprev[2];
    float gxc[3][2];
    {
        char* AH0 = sm + RSM_A;
        size_t ib = (size_t)(b0 + b) * T_;
        int f0 = wm ? (ii32[ib] != 0u) : (ii8[ib] != 0);
        float2 v = *(const float2*)&hx[(size_t)(b0 + b) * HD + j_g];
        if (f0) { v.x = 0.f; v.y = 0.f; }
        hprev[0] = v.x; hprev[1] = v.y;
        stA2_both(AH0, aab_peer, b, j_g, v);
        #pragma unroll
        for (int g = 0; g < 3; g++) {
            float2 gv = *(const float2*)&g_gates[ib * G3 + g * 128 + j_g];
            gxc[g][0] = gv.x; gxc[g][1] = gv.y;
        }
    }

    asm volatile("barrier.cluster.arrive.aligned;" ::: "memory");
    asm volatile("barrier.cluster.wait.aligned;" ::: "memory");

    const int arow = lane & 15;
    const uint32_t abase = (uint32_t)(arow * 256);
    const int achx = (lane & 16) ? 1 : 0, arx = arow & 7;
    const int nrl = 8 * wr + (lane & 7);
    const int kc = lane >> 3;

    // ---- hoist W fragments (constant across all timesteps) ----
    uint32_t wbh[2][3][4], wbl[2][3][4];
    #pragma unroll
    for (int kkl = 0; kkl < 2; kkl++) {
        const int kk = 2 * kh + kkl;
        #pragma unroll
        for (int g = 0; g < 3; g++) {
            int row_local = (g << 6) + nrl;
            uint32_t chunk = (uint32_t)((4 * kk + kc) ^ (lane & 7));
            uint32_t boff = (uint32_t)(row_local * 256) + (chunk << 4);
            ldsm_x4(wbh[kkl][g], whb + boff);
            ldsm_x4(wbl[kkl][g], wlb + boff);
        }
    }

    const int pub_slot  = ((kh * 8 + wr) * 32 + lane) * 6;
    const int read_slot = (((1 - kh) * 8 + wr) * 32 + lane) * 6;

    int cur = 0;
    for (int t = 0; t < T_; t++) {
        // prefetch next gx + flag (global loads issued before the cluster wait)
        float ngx[3][2];
        int nf = 0;
        if (t + 1 < T_) {
            size_t ib = (size_t)(b0 + b) * T_ + (t + 1);
            nf = wm ? (ii32[ib] != 0u) : (ii8[ib] != 0);
            #pragma unroll
            for (int g = 0; g < 3; g++) {
                float2 gv = *(const float2*)&g_gates[ib * G3 + g * 128 + j_g];
                ngx[g][0] = gv.x; ngx[g][1] = gv.y;
            }
        }

        // wait for A(cur) completeness (stores from step t-1, both CTAs)
        if (t > 0) MBAR_WAIT_CL(mbar, (uint32_t)((t - 1) & 1));

        // ---- MMA over this warp's k-half, W fragments from registers ----
        float acc[3][4];
        #pragma unroll
        for (int g = 0; g < 3; g++) { acc[g][0]=acc[g][1]=acc[g][2]=acc[g][3]=0.f; }
        const uint32_t ahb = aab + (uint32_t)cur * 8192;
        const uint32_t alb = ahb + 4096;
        #pragma unroll
        for (int kkl = 0; kkl < 2; kkl++) {
            const int kk = 2 * kh + kkl;
            uint32_t ah4[2][4], al4[2][4];
            #pragma unroll
            for (int s = 0; s < 2; s++) {
                int k0 = 2 * kk + s;
                uint32_t ach = (uint32_t)((2 * k0 + achx) ^ arx);
                ldsm_x4(ah4[s], ahb + abase + (ach << 4));
                ldsm_x4(al4[s], alb + abase + (ach << 4));
            }
            #pragma unroll
            for (int g = 0; g < 3; g++) {
                #pragma unroll
                for (int s = 0; s < 2; s++) {
                    mma16816(acc[g], ah4[s], wbh[kkl][g] + 2 * s);
                    mma16816(acc[g], ah4[s], wbl[kkl][g] + 2 * s);
                    mma16816(acc[g], al4[s], wbh[kkl][g] + 2 * s);
                }
            }
        }

        {
            const int pix = 2 * (1 - kh);
            #pragma unroll
            for (int g = 0; g < 3; g++) {
                Pbuf[pub_slot + 2 * g]     = acc[g][pix];
                Pbuf[pub_slot + 2 * g + 1] = acc[g][pix + 1];
            }
        }
        __syncthreads();

        const int nxt = cur ^ 1;
        char* AHn = sm + RSM_A + nxt * 8192;
        uint32_t pAHn = aab_peer + (uint32_t)nxt * 8192;
        float hn_[2];
        #pragma unroll
        for (int q = 0; q < 2; q++) {
            const int ix = 2 * kh + q;
            float a0 = acc[0][ix] + Pbuf[read_slot + 0 + q] + bv[0][q];
            float a1 = acc[1][ix] + Pbuf[read_slot + 2 + q] + bv[1][q];
            float a2 = acc[2][ix] + Pbuf[read_slot + 4 + q] + bv[2][q];
            float rr = sigf(gxc[0][q] + a0);
            float zz = sigf(gxc[1][q] + a1);
            float nn = tanhf_fast(gxc[2][q] + rr * a2);
            hn_[q] = (1.f - zz) * nn + zz * hprev[q];
        }
        *(float2*)&g_y[((size_t)(b0 + b) * T_ + t) * HD + j_g] = make_float2(hn_[0], hn_[1]);
        if (t + 1 < T_) {
            float2 he = nf ? make_float2(0.f, 0.f) : make_float2(hn_[0], hn_[1]);
            hprev[0] = he.x; hprev[1] = he.y;
            stA2_both(AHn, pAHn, b, j_g, he);
            #pragma unroll
            for (int g = 0; g < 3; g++) { gxc[g][0] = ngx[g][0]; gxc[g][1] = ngx[g][1]; }

            __syncthreads();
            if (tid == 0) {
                MBAR_ARRIVE_LOCAL(mbar);
                MBAR_ARRIVE_REMOTE(mbar_peer);
            }
            // wait moved to top of next iteration (after gx prefetch issue)
        } else {
            *(float2*)&hxout[(size_t)(b0 + b) * HD + j_g] = make_float2(hn_[0], hn_[1]);
        }
        cur = nxt;
    }
}

// ---------------- out: 256 threads (R14, unchanged) ----------------
#define OSM_AH  0
#define OSM_AL  (128 * ASTR * 2)
#define OSM_BH  (2 * 128 * ASTR * 2)
#define OSM_BL  (OSM_BH + 64 * ASTR * 2)
#define OSM_TOT (OSM_BH + 2 * 64 * ASTR * 2)

__global__ void __launch_bounds__(256, 2) out_kernel(
    const float* __restrict__ bout, float* __restrict__ out)
{
    extern __shared__ char smem[];
    __nv_bfloat16* Ah = (__nv_bfloat16*)(smem + OSM_AH);
    __nv_bfloat16* Al = (__nv_bfloat16*)(smem + OSM_AL);
    __nv_bfloat16* Bh = (__nv_bfloat16*)(smem + OSM_BH);
    __nv_bfloat16* Bl = (__nv_bfloat16*)(smem + OSM_BL);
    const uint32_t a_hi = smem_u32(Ah), a_lo = smem_u32(Al);
    const uint32_t b_hi = smem_u32(Bh), b_lo = smem_u32(Bl);
    const int tid = threadIdx.x, warp = tid >> 5, lane = tid & 31;
    const size_t base = (size_t)blockIdx.x * 128;

    for (int p = tid; p < 128 * 64; p += 256) {
        int row = p >> 6, kp = p & 63;
        float2 v = *(const float2*)&g_y[(base + row) * HD + 2 * kp];
        split2(Ah, Al, row * ASTR + 2 * kp, v.x, v.y);
    }
    load_wsplit<HD, 256>(g_wo_h, g_wo_l, Bh, Bl, 64, tid);
    __syncthreads();

    float acc[8][4];
    #pragma unroll
    for (int j = 0; j < 8; j++) { acc[j][0]=acc[j][1]=acc[j][2]=acc[j][3]=0.f; }

    const int arow = 16 * warp + (lane & 7) + ((lane & 8) ? 8 : 0);
    const int acg  = (lane & 16) ? 8 : 0;
    const uint32_t aoff = (uint32_t)(arow * ASTR + acg) * 2;
    const int nloc = (lane & 7) + ((lane & 16) ? 8 : 0);
    const int bkg  = (lane & 8) ? 8 : 0;
    const uint32_t boff = (uint32_t)(nloc * ASTR + bkg) * 2;
    #pragma unroll
    for (int k0 = 0; k0 < 8; k0++) {
        uint32_t ah[4], al[4];
        ldsm_x4(ah, a_hi + aoff + k0 * 32);
        ldsm_x4(al, a_lo + aoff + k0 * 32);
        #pragma unroll
        for (int jp = 0; jp < 4; jp++) {
            uint32_t bo = boff + (uint32_t)(jp * 16 * ASTR) * 2 + k0 * 32;
            uint32_t bh[4], bl[4];
            ldsm_x4(bh, b_hi + bo);
            ldsm_x4(bl, b_lo + bo);
            mma16816(acc[2*jp],     ah, bh);
            mma16816(acc[2*jp],     ah, bl);
            mma16816(acc[2*jp],     al, bh);
            mma16816(acc[2*jp + 1], ah, bh + 2);
            mma16816(acc[2*jp + 1], ah, bl + 2);
            mma16816(acc[2*jp + 1], al, bh + 2);
        }
    }

    const int r0 = 16 * warp + (lane >> 2), r1 = r0 + 8;
    #pragma unroll
    for (int j = 0; j < 8; j++) {
        int col = 8 * j + 2 * (lane & 3);
        float bv0 = __ldg(&bout[col]), bv1 = __ldg(&bout[col + 1]);
        *(float2*)&out[(base + r0) * OD + col] = make_float2(acc[j][0] + bv0, acc[j][1] + bv1);
        *(float2*)&out[(base + r1) * OD + col] = make_float2(acc[j][2] + bv0, acc[j][3] + bv1);
    }
}

// ---------------- launcher ----------------
extern "C" void kernel_launch(void* const* d_in, const int* in_sizes, int n_in,
                              void* d_out, int out_size)
{
    const float* x    = (const float*)d_in[0];
    const void*  isin = d_in[1];
    const float* hx   = (const float*)d_in[2];
    const float* W1   = (const float*)d_in[3];
    const float* b1   = (const float*)d_in[4];
    const float* g1   = (const float*)d_in[5];
    const float* be1  = (const float*)d_in[6];
    const float* W2   = (const float*)d_in[7];
    const float* b2   = (const float*)d_in[8];
    const float* g2   = (const float*)d_in[9];
    const float* be2  = (const float*)d_in[10];
    const float* Wih  = (const float*)d_in[11];
    const float* Whh  = (const float*)d_in[12];
    const float* bih  = (const float*)d_in[13];
    const float* bhh  = (const float*)d_in[14];
    const float* Wout = (const float*)d_in[15];
    const float* bout = (const float*)d_in[16];
    float* out = (float*)d_out;

    cudaFuncSetAttribute(ff_kernel,  cudaFuncAttributeMaxDynamicSharedMemorySize, SM_TOT);
    cudaFuncSetAttribute(rec_kernel, cudaFuncAttributeMaxDynamicSharedMemorySize, RSM_TOT);
    cudaFuncSetAttribute(out_kernel, cudaFuncAttributeMaxDynamicSharedMemorySize, OSM_TOT);

    detect_kernel<<<1, 256>>>((const unsigned int*)isin);
    prep_kernel<<<160, 512>>>(W1, W2, Wih, Wout);
    ff_kernel<<<BT_ / 128, 512, SM_TOT>>>(x, b1, g1, be1, b2, g2, be2, bih);
    rec_kernel<<<128, 512, RSM_TOT>>>(hx, Whh, bhh, isin, out + (size_t)BT_ * OD);
    out_kernel<<<BT_ / 128, 256, OSM_TOT>>>(bout, out);
}